// round 1
// baseline (speedup 1.0000x reference)
#include <cuda_runtime.h>
#include <cuda_bf16.h>
#include <cstdint>

// ---------------------------------------------------------------------------
// PredictiveCodingNet: 20-step linear recurrence collapsed analytically.
//   s_i(final) = u @ P_i + q_i,  u = x @ W1^T + b1
// P/q recursions iterated on-device (20 small launches), then two GEMMs.
// ---------------------------------------------------------------------------

#define BATCH   65536
#define IN_DIM  784
#define H1      128
#define H2      64
#define H3      32
#define OUT_D   10
#define NCOLS   234          // H1+H2+H3+OUT
#define NPAD    256

// ---- device scratch (static; no allocations) ----
__device__ float g_P1[2][H1*H1];
__device__ float g_P2[2][H1*H2];
__device__ float g_P3[2][H1*H3];
__device__ float g_P4[2][H1*OUT_D];
__device__ float g_q2[2][H2];
__device__ float g_q3[2][H3];
__device__ float g_q4[2][OUT_D];
__device__ float g_Pcat[H1*NPAD];
__device__ float g_qcat[NPAD];
__device__ float g_u[(size_t)BATCH*H1];   // 32 MB intermediate

// ---------------------------------------------------------------------------
__global__ void init_precomp() {
    int t = blockIdx.x*256 + threadIdx.x;
    for (int i = t; i < H1*H1;   i += gridDim.x*256) g_P1[0][i] = 0.f;
    for (int i = t; i < H1*H2;   i += gridDim.x*256) g_P2[0][i] = 0.f;
    for (int i = t; i < H1*H3;   i += gridDim.x*256) g_P3[0][i] = 0.f;
    for (int i = t; i < H1*OUT_D;i += gridDim.x*256) g_P4[0][i] = 0.f;
    if (t < H2) g_q2[0][t] = 0.f;
    if (t < H3) g_q3[0][t] = 0.f;
    if (t < OUT_D) g_q4[0][t] = 0.1f;   // softmax(zeros) = 1/10
}

// One step of the affine-map recursion. Reads parity p, writes p^1.
//   A_i = 0.8 I + 0.2 L_i  (applied from the right)
__global__ void step_precomp(int p,
                             const float* __restrict__ W2, const float* __restrict__ W3,
                             const float* __restrict__ W4,
                             const float* __restrict__ L1, const float* __restrict__ L2,
                             const float* __restrict__ L3,
                             const float* __restrict__ b2, const float* __restrict__ b3,
                             const float* __restrict__ b4) {
    int t = blockIdx.x*256 + threadIdx.x;
    const float* P1o = g_P1[p]; float* P1n = g_P1[p^1];
    const float* P2o = g_P2[p]; float* P2n = g_P2[p^1];
    const float* P3o = g_P3[p]; float* P3n = g_P3[p^1];
    const float* P4o = g_P4[p]; float* P4n = g_P4[p^1];

    if (t < H1*H1) {                       // P1' = 0.8 P1 + 0.2 P1 L1 + 0.2 I
        int r = t >> 7, c = t & 127;
        float acc = 0.f;
        #pragma unroll 4
        for (int k = 0; k < H1; k++) acc += P1o[r*H1+k] * L1[k*H1+c];
        P1n[t] = 0.8f*P1o[t] + 0.2f*acc + ((r==c) ? 0.2f : 0.f);
    } else if (t < H1*H1 + H1*H2) {        // P2' = 0.8 P2 + 0.2(P1 W2^T + P2 L2)
        int s = t - H1*H1; int r = s >> 6, c = s & 63;
        float a1 = 0.f, a2 = 0.f;
        #pragma unroll 4
        for (int k = 0; k < H1; k++) a1 += P1o[r*H1+k] * W2[c*H1+k];
        #pragma unroll 4
        for (int k = 0; k < H2; k++) a2 += P2o[r*H2+k] * L2[k*H2+c];
        P2n[s] = 0.8f*P2o[s] + 0.2f*(a1 + a2);
    } else if (t < H1*H1 + H1*H2 + H1*H3) {  // P3'
        int s = t - (H1*H1 + H1*H2); int r = s >> 5, c = s & 31;
        float a1 = 0.f, a2 = 0.f;
        #pragma unroll 4
        for (int k = 0; k < H2; k++) a1 += P2o[r*H2+k] * W3[c*H2+k];
        #pragma unroll 4
        for (int k = 0; k < H3; k++) a2 += P3o[r*H3+k] * L3[k*H3+c];
        P3n[s] = 0.8f*P3o[s] + 0.2f*(a1 + a2);
    } else if (t < H1*H1 + H1*H2 + H1*H3 + H1*OUT_D) {  // P4' = 0.8 P4 + 0.2 P3 W4^T
        int s = t - (H1*H1 + H1*H2 + H1*H3); int r = s / OUT_D, c = s % OUT_D;
        float a1 = 0.f;
        #pragma unroll 4
        for (int k = 0; k < H3; k++) a1 += P3o[r*H3+k] * W4[c*H3+k];
        P4n[s] = 0.8f*P4o[s] + 0.2f*a1;
    } else {
        int base = H1*H1 + H1*H2 + H1*H3 + H1*OUT_D;
        if (t < base + H2) {               // q2' = 0.8 q2 + 0.2(q2 L2 + b2)
            int c = t - base;
            float a2 = 0.f;
            for (int k = 0; k < H2; k++) a2 += g_q2[p][k] * L2[k*H2+c];
            g_q2[p^1][c] = 0.8f*g_q2[p][c] + 0.2f*(a2 + b2[c]);
        } else if (t < base + H2 + H3) {   // q3' = 0.8 q3 + 0.2(q2 W3^T + b3 + q3 L3)
            int c = t - base - H2;
            float a1 = 0.f, a2 = 0.f;
            for (int k = 0; k < H2; k++) a1 += g_q2[p][k] * W3[c*H2+k];
            for (int k = 0; k < H3; k++) a2 += g_q3[p][k] * L3[k*H3+c];
            g_q3[p^1][c] = 0.8f*g_q3[p][c] + 0.2f*(a1 + a2 + b3[c]);
        } else if (t < base + H2 + H3 + OUT_D) {  // q4' = 0.8 q4 + 0.2(q3 W4^T + b4)
            int c = t - base - H2 - H3;
            float a1 = 0.f;
            for (int k = 0; k < H3; k++) a1 += g_q3[p][k] * W4[c*H3+k];
            g_q4[p^1][c] = 0.8f*g_q4[p][c] + 0.2f*(a1 + b4[c]);
        }
    }
}

// Concatenate final P / q (in buffer 0 after 20 steps) into padded [128,256].
__global__ void pack_precomp() {
    int t = blockIdx.x*256 + threadIdx.x;   // 128*256 threads
    int k = t >> 8, c = t & 255;
    float v = 0.f;
    if      (c < H1)            v = g_P1[0][k*H1 + c];
    else if (c < H1+H2)         v = g_P2[0][k*H2 + (c-H1)];
    else if (c < H1+H2+H3)      v = g_P3[0][k*H3 + (c-H1-H2)];
    else if (c < NCOLS)         v = g_P4[0][k*OUT_D + (c-H1-H2-H3)];
    g_Pcat[k*NPAD + c] = v;
    if (k == 0) {
        float q = 0.f;
        if      (c >= H1 && c < H1+H2)      q = g_q2[0][c-H1];
        else if (c >= H1+H2 && c < H1+H2+H3) q = g_q3[0][c-H1-H2];
        else if (c >= H1+H2+H3 && c < NCOLS) q = g_q4[0][c-H1-H2-H3];
        g_qcat[c] = q;
    }
}

// ---------------------------------------------------------------------------
// GEMM1: u[B,128] = x[B,784] @ W1^T[784,128] + b1   (both operands K-contig)
// Tile 128x128, BK=16, 256 threads, 8x8 micro-tiles.
// ---------------------------------------------------------------------------
__global__ __launch_bounds__(256) void gemm1(const float* __restrict__ x,
                                             const float* __restrict__ W1,
                                             const float* __restrict__ b1) {
    __shared__ float As[16][132];   // x^T  : As[k][m]
    __shared__ float Bs[16][132];   // W1^T : Bs[k][n]
    const int m0  = blockIdx.x * 128;
    const int tid = threadIdx.x;
    const int tx  = tid & 15, ty = tid >> 4;

    float acc[8][8];
    #pragma unroll
    for (int i = 0; i < 8; i++)
        #pragma unroll
        for (int j = 0; j < 8; j++) acc[i][j] = 0.f;

    for (int k0 = 0; k0 < IN_DIM; k0 += 16) {
        #pragma unroll
        for (int q = 0; q < 2; q++) {
            int f   = tid*2 + q;            // 0..511
            int row = f >> 2;               // 0..127
            int kc  = (f & 3) * 4;          // 0,4,8,12
            float4 v = *(const float4*)(x  + (size_t)(m0+row)*IN_DIM + k0 + kc);
            As[kc+0][row]=v.x; As[kc+1][row]=v.y; As[kc+2][row]=v.z; As[kc+3][row]=v.w;
            float4 w = *(const float4*)(W1 + (size_t)row*IN_DIM + k0 + kc);
            Bs[kc+0][row]=w.x; Bs[kc+1][row]=w.y; Bs[kc+2][row]=w.z; Bs[kc+3][row]=w.w;
        }
        __syncthreads();
        #pragma unroll
        for (int kk = 0; kk < 16; kk++) {
            float4 a0 = *(const float4*)&As[kk][ty*8];
            float4 a1 = *(const float4*)&As[kk][ty*8+4];
            float4 b0 = *(const float4*)&Bs[kk][tx*8];
            float4 b1v= *(const float4*)&Bs[kk][tx*8+4];
            float a[8] = {a0.x,a0.y,a0.z,a0.w,a1.x,a1.y,a1.z,a1.w};
            float b[8] = {b0.x,b0.y,b0.z,b0.w,b1v.x,b1v.y,b1v.z,b1v.w};
            #pragma unroll
            for (int i = 0; i < 8; i++)
                #pragma unroll
                for (int j = 0; j < 8; j++) acc[i][j] += a[i]*b[j];
        }
        __syncthreads();
    }
    float bias[8];
    #pragma unroll
    for (int j = 0; j < 8; j++) bias[j] = b1[tx*8+j];
    #pragma unroll
    for (int i = 0; i < 8; i++) {
        size_t rowoff = (size_t)(m0 + ty*8 + i) * H1 + tx*8;
        #pragma unroll
        for (int j = 0; j < 8; j++) g_u[rowoff + j] = acc[i][j] + bias[j];
    }
}

// ---------------------------------------------------------------------------
// GEMM2: out = u[B,128] @ Pcat[128,256] + qcat, scattered into 4 blocks.
// Tile 128x128, BK=32, grid (512,2).
// ---------------------------------------------------------------------------
__global__ __launch_bounds__(256) void gemm2(float* __restrict__ out) {
    __shared__ float As[32][132];   // u^T
    __shared__ float Bs[32][132];   // Pcat
    const int m0  = blockIdx.x * 128;
    const int n0  = blockIdx.y * 128;
    const int tid = threadIdx.x;
    const int tx  = tid & 15, ty = tid >> 4;

    float acc[8][8];
    #pragma unroll
    for (int i = 0; i < 8; i++)
        #pragma unroll
        for (int j = 0; j < 8; j++) acc[i][j] = 0.f;

    for (int k0 = 0; k0 < H1; k0 += 32) {
        #pragma unroll
        for (int q = 0; q < 4; q++) {
            int f   = tid*4 + q;            // 0..1023
            int row = f >> 3;               // 0..127
            int kc  = (f & 7) * 4;          // 0..28
            float4 v = *(const float4*)(g_u + (size_t)(m0+row)*H1 + k0 + kc);
            As[kc+0][row]=v.x; As[kc+1][row]=v.y; As[kc+2][row]=v.z; As[kc+3][row]=v.w;
        }
        #pragma unroll
        for (int q = 0; q < 4; q++) {
            int f   = tid*4 + q;
            int row = f >> 5;               // 0..31
            int nc  = (f & 31) * 4;         // 0..124
            float4 v = *(const float4*)(g_Pcat + (size_t)(k0+row)*NPAD + n0 + nc);
            *(float4*)&Bs[row][nc] = v;
        }
        __syncthreads();
        #pragma unroll
        for (int kk = 0; kk < 32; kk++) {
            float4 a0 = *(const float4*)&As[kk][ty*8];
            float4 a1 = *(const float4*)&As[kk][ty*8+4];
            float4 b0 = *(const float4*)&Bs[kk][tx*8];
            float4 b1v= *(const float4*)&Bs[kk][tx*8+4];
            float a[8] = {a0.x,a0.y,a0.z,a0.w,a1.x,a1.y,a1.z,a1.w};
            float b[8] = {b0.x,b0.y,b0.z,b0.w,b1v.x,b1v.y,b1v.z,b1v.w};
            #pragma unroll
            for (int i = 0; i < 8; i++)
                #pragma unroll
                for (int j = 0; j < 8; j++) acc[i][j] += a[i]*b[j];
        }
        __syncthreads();
    }

    // epilogue: scatter column c into the right output block, add q
    #pragma unroll
    for (int j = 0; j < 8; j++) {
        int c = n0 + tx*8 + j;
        if (c >= NCOLS) continue;
        float qv = g_qcat[c];
        size_t base; int width; int cc;
        if (c < H1)              { base = 0;                              width = H1;   cc = c; }
        else if (c < H1+H2)      { base = (size_t)BATCH*H1;               width = H2;   cc = c-H1; }
        else if (c < H1+H2+H3)   { base = (size_t)BATCH*(H1+H2);          width = H3;   cc = c-H1-H2; }
        else                     { base = (size_t)BATCH*(H1+H2+H3);       width = OUT_D;cc = c-H1-H2-H3; }
        #pragma unroll
        for (int i = 0; i < 8; i++) {
            int m = m0 + ty*8 + i;
            out[base + (size_t)m*width + cc] = acc[i][j] + qv;
        }
    }
}

// ---------------------------------------------------------------------------
extern "C" void kernel_launch(void* const* d_in, const int* in_sizes, int n_in,
                              void* d_out, int out_size) {
    const float* x  = (const float*)d_in[0];
    const float* W1 = (const float*)d_in[1];
    const float* W2 = (const float*)d_in[2];
    const float* W3 = (const float*)d_in[3];
    const float* W4 = (const float*)d_in[4];
    const float* L1 = (const float*)d_in[5];
    const float* L2 = (const float*)d_in[6];
    const float* L3 = (const float*)d_in[7];
    const float* b1 = (const float*)d_in[8];
    const float* b2 = (const float*)d_in[9];
    const float* b3 = (const float*)d_in[10];
    const float* b4 = (const float*)d_in[11];
    float* out = (float*)d_out;

    init_precomp<<<128, 256>>>();
    const int tot = H1*H1 + H1*H2 + H1*H3 + H1*OUT_D + H2 + H3 + OUT_D;
    for (int i = 0; i < 20; i++)
        step_precomp<<<(tot+255)/256, 256>>>(i & 1, W2, W3, W4, L1, L2, L3, b2, b3, b4);
    pack_precomp<<<128, 256>>>();

    gemm1<<<BATCH/128, 256>>>(x, W1, b1);
    gemm2<<<dim3(BATCH/128, 2), 256>>>(out);
}